// round 2
// baseline (speedup 1.0000x reference)
#include <cuda_runtime.h>
#include <cstdint>
#include <math.h>

#define EPS   1e-5f
#define BB    2
#define NN    512
#define DD    64
#define TI    32      // i-rows per block
#define TJ    16      // j-cols per block

typedef unsigned long long ull;

// ---------------- device scratch (no allocations allowed) ----------------
__device__ __align__(16) float g_U   [BB*NN*128];     // s1 * (W1a @ f_i), row-major [node][128]
__device__ __align__(16) float g_Vt  [BB*128*NN];     // k-major: [b][k][j] = s1*(W1b@f_j)+bias
__device__ __align__(16) float g_nfn [BB*NN*DD];      // normalized node features
__device__ __align__(16) float g_W2t [128*64];        // k-major, BN-folded: [k][o]
__device__ __align__(16) float g_W3t [64*32];         // k-major, BN-folded: [kk][o]
__device__ float g_c2[64];
__device__ float g_c3[32];
__device__ float g_w4[32];
__device__ float g_b4s;
__device__ __align__(16) float g_L   [BB*NN*NN];      // raw MLP logits
__device__ int   g_active[BB];

// ---------------- fp32x2 packed helpers (sm_103a) ----------------
__device__ __forceinline__ void fma2(ull &d, ull a, ull b) {
    asm("fma.rn.f32x2 %0, %1, %2, %0;" : "+l"(d) : "l"(a), "l"(b));
}
__device__ __forceinline__ ull pack2(float x) {
    ull r; unsigned u = __float_as_uint(x);
    asm("mov.b64 %0, {%1, %1};" : "=l"(r) : "r"(u));
    return r;
}
__device__ __forceinline__ void unpack2(ull v, float &lo, float &hi) {
    unsigned a, b;
    asm("mov.b64 {%0, %1}, %2;" : "=r"(a), "=r"(b) : "l"(v));
    lo = __uint_as_float(a); hi = __uint_as_float(b);
}

// ---------------- prep: fold BN into W2/W3, bias constants ----------------
__global__ void k_fold(const float* __restrict__ W2, const float* __restrict__ b2,
                       const float* __restrict__ g2, const float* __restrict__ be2,
                       const float* __restrict__ m2, const float* __restrict__ v2,
                       const float* __restrict__ W3, const float* __restrict__ b3,
                       const float* __restrict__ g3, const float* __restrict__ be3,
                       const float* __restrict__ m3, const float* __restrict__ v3,
                       const float* __restrict__ W4, const float* __restrict__ b4) {
    int t = threadIdx.x;
    for (int idx = t; idx < 64 * 128; idx += blockDim.x) {
        int o = idx / 128, k = idx % 128;
        float s = g2[o] * rsqrtf(v2[o] + EPS);
        g_W2t[k * 64 + o] = W2[o * 128 + k] * s;
    }
    for (int idx = t; idx < 32 * 64; idx += blockDim.x) {
        int o = idx / 64, k = idx % 64;
        float s = g3[o] * rsqrtf(v3[o] + EPS);
        g_W3t[k * 32 + o] = W3[o * 64 + k] * s;
    }
    if (t < 64) {
        float s = g2[t] * rsqrtf(v2[t] + EPS);
        g_c2[t] = (b2[t] - m2[t]) * s + be2[t];
    }
    if (t < 32) {
        float s = g3[t] * rsqrtf(v3[t] + EPS);
        g_c3[t] = (b3[t] - m3[t]) * s + be3[t];
        g_w4[t] = W4[t];
    }
    if (t == 0) g_b4s = b4[0];
}

// ---------------- prep: per-node U, Vt (transposed), normalized features ----
__global__ void k_nodes(const float* __restrict__ f,
                        const float* __restrict__ W1, const float* __restrict__ b1,
                        const float* __restrict__ g1, const float* __restrict__ be1,
                        const float* __restrict__ m1, const float* __restrict__ v1) {
    __shared__ float fs[DD];
    __shared__ float sinv;
    int node = blockIdx.x;                 // b*NN + i
    int b = node / NN, i = node % NN;
    int t = threadIdx.x;                   // 0..127 = output channel o
    if (t < DD) fs[t] = f[node * DD + t];
    __syncthreads();
    if (t == 0) {
        float ss = 0.f;
        for (int d = 0; d < DD; d++) ss += fs[d] * fs[d];
        sinv = 1.f / fmaxf(sqrtf(ss), 1e-12f);
    }
    __syncthreads();
    if (t < DD) g_nfn[node * DD + t] = fs[t] * sinv;

    float s1 = g1[t] * rsqrtf(v1[t] + EPS);
    float u = 0.f, vv = 0.f;
    const float* wr = &W1[t * 128];
    #pragma unroll 8
    for (int d = 0; d < DD; d++) {
        u  += wr[d]      * fs[d];
        vv += wr[DD + d] * fs[d];
    }
    g_U[node * 128 + t] = u * s1;
    g_Vt[(b * 128 + t) * NN + i] = vv * s1 + (b1[t] - m1[t]) * s1 + be1[t];
}

// ---------------- prep: per-batch active flag (n_valid > 1) ----------------
__global__ void k_active(const int* __restrict__ masks) {
    __shared__ int cnt[BB];
    int t = threadIdx.x;
    if (t < BB) cnt[t] = 0;
    __syncthreads();
    for (int idx = t; idx < BB * NN; idx += blockDim.x)
        if (masks[idx] != 0) atomicAdd(&cnt[idx / NN], 1);
    __syncthreads();
    if (t < BB) g_active[t] = (cnt[t] > 1) ? 1 : 0;
}

// ---------------- main: fused 3-layer MLP, 32x16 pair tiles, 2 pairs/thread --
__global__ __launch_bounds__(256)
void k_main() {
    __shared__ ull   W2s[128][32];     // 32KB  [k][q] = outputs (2q, 2q+1)
    __shared__ ull   W3s[64][16];      // 8KB   [kk][r] = outputs (2r, 2r+1)
    __shared__ float c2s[64], c3s[32], w4s[32];
    __shared__ float b4sh;

    int b  = blockIdx.z;
    int i0 = blockIdx.y * TI;
    int j0 = blockIdx.x * TJ;
    int t  = threadIdx.x;

    {
        const ull* w2g = (const ull*)g_W2t;
        ull* w2s = &W2s[0][0];
        for (int idx = t; idx < 128 * 32; idx += 256) w2s[idx] = w2g[idx];
        const ull* w3g = (const ull*)g_W3t;
        ull* w3s = &W3s[0][0];
        for (int idx = t; idx < 64 * 16; idx += 256) w3s[idx] = w3g[idx];
        if (t < 64) c2s[t] = g_c2[t];
        if (t < 32) { c3s[t] = g_c3[t]; w4s[t] = g_w4[t]; }
        if (t == 0) b4sh = g_b4s;
    }
    __syncthreads();

    int ty = t >> 4, tx = t & 15;
    int ia = i0 + ty;           // first pair row
    int ib = i0 + ty + 16;      // second pair row
    int j  = j0 + tx;

    const float4* Ua4 = (const float4*)&g_U[(b * NN + ia) * 128];
    const float4* Ub4 = (const float4*)&g_U[(b * NN + ib) * 128];
    const float*  Vp  = &g_Vt[(b * 128) * NN + j];   // advance by k*NN

    ull A0[32], A1[32];
    #pragma unroll
    for (int q = 0; q < 32; q++) { A0[q] = 0ull; A1[q] = 0ull; }

    // ---- Layer 2: h2[64] += W2t[k][:] * relu(U[k] + V[k]) ----
    #pragma unroll 2
    for (int k4 = 0; k4 < 32; k4++) {
        float4 ua = __ldg(Ua4 + k4);
        float4 ub = __ldg(Ub4 + k4);
        float va[4] = { (&ua.x)[0], (&ua.x)[1], (&ua.x)[2], (&ua.x)[3] };
        float vb[4] = { (&ub.x)[0], (&ub.x)[1], (&ub.x)[2], (&ub.x)[3] };
        float vv[4];
        vv[0] = __ldg(Vp + (4 * k4 + 0) * NN);
        vv[1] = __ldg(Vp + (4 * k4 + 1) * NN);
        vv[2] = __ldg(Vp + (4 * k4 + 2) * NN);
        vv[3] = __ldg(Vp + (4 * k4 + 3) * NN);
        #pragma unroll
        for (int s = 0; s < 4; s++) {
            int k = 4 * k4 + s;
            float aa = fmaxf(va[s] + vv[s], 0.f);
            float ab = fmaxf(vb[s] + vv[s], 0.f);
            ull pa = pack2(aa), pb = pack2(ab);
            const ulonglong2* w = (const ulonglong2*)&W2s[k][0];
            #pragma unroll
            for (int q2 = 0; q2 < 16; q2++) {
                ulonglong2 ww = w[q2];
                fma2(A0[2 * q2],     pa, ww.x);
                fma2(A0[2 * q2 + 1], pa, ww.y);
                fma2(A1[2 * q2],     pb, ww.x);
                fma2(A1[2 * q2 + 1], pb, ww.y);
            }
        }
    }

    // ---- Layer 3: h3[32] += W3t[kk][:] * relu(h2[kk] + c2[kk]) ----
    ull B0[16], B1[16];
    #pragma unroll
    for (int r = 0; r < 16; r++) { B0[r] = 0ull; B1[r] = 0ull; }

    #pragma unroll 4
    for (int q = 0; q < 32; q++) {
        float x0, x1, y0, y1;
        unpack2(A0[q], x0, x1);
        unpack2(A1[q], y0, y1);
        #pragma unroll
        for (int h = 0; h < 2; h++) {
            int kk = 2 * q + h;
            float e0 = fmaxf((h ? x1 : x0) + c2s[kk], 0.f);
            float e1 = fmaxf((h ? y1 : y0) + c2s[kk], 0.f);
            ull p0 = pack2(e0), p1 = pack2(e1);
            const ulonglong2* w = (const ulonglong2*)&W3s[kk][0];
            #pragma unroll
            for (int r2 = 0; r2 < 8; r2++) {
                ulonglong2 ww = w[r2];
                fma2(B0[2 * r2],     p0, ww.x);
                fma2(B0[2 * r2 + 1], p0, ww.y);
                fma2(B1[2 * r2],     p1, ww.x);
                fma2(B1[2 * r2 + 1], p1, ww.y);
            }
        }
    }

    // ---- Head: logit = w4 . relu(h3 + c3) + b4 ----
    float l0 = b4sh, l1 = b4sh;
    #pragma unroll
    for (int r = 0; r < 16; r++) {
        float f0, f1, h0, h1;
        unpack2(B0[r], f0, f1);
        unpack2(B1[r], h0, h1);
        l0 += fmaxf(f0 + c3s[2 * r],     0.f) * w4s[2 * r];
        l0 += fmaxf(f1 + c3s[2 * r + 1], 0.f) * w4s[2 * r + 1];
        l1 += fmaxf(h0 + c3s[2 * r],     0.f) * w4s[2 * r];
        l1 += fmaxf(h1 + c3s[2 * r + 1], 0.f) * w4s[2 * r + 1];
    }

    g_L[(b * NN + ia) * NN + j] = l0;
    g_L[(b * NN + ib) * NN + j] = l1;
}

// ---------------- epilogue: symmetrize + sim + sigmoid + masks ----------------
__global__ void k_epi(const int* __restrict__ masks, float* __restrict__ out,
                      int write_logits) {
    __shared__ float LT [32][33];
    __shared__ float nfI[32][65];
    __shared__ float nfJ[32][65];
    int b  = blockIdx.z;
    int i0 = blockIdx.y * 32;
    int j0 = blockIdx.x * 32;
    int tx = threadIdx.x, ty = threadIdx.y;

    LT[ty][tx] = g_L[(b * NN + j0 + ty) * NN + (i0 + tx)];
    nfI[ty][tx]      = g_nfn[(b * NN + i0 + ty) * DD + tx];
    nfI[ty][tx + 32] = g_nfn[(b * NN + i0 + ty) * DD + tx + 32];
    nfJ[ty][tx]      = g_nfn[(b * NN + j0 + ty) * DD + tx];
    nfJ[ty][tx + 32] = g_nfn[(b * NN + j0 + ty) * DD + tx + 32];
    __syncthreads();

    int i = i0 + ty, j = j0 + tx;
    float lij = g_L[(b * NN + i) * NN + j];
    float lji = LT[tx][ty];
    float lsym = (i == j) ? -10.f : 0.5f * (lij + lji);

    float sim = 0.f;
    #pragma unroll
    for (int d = 0; d < DD; d++) sim += nfI[ty][d] * nfJ[tx][d];

    float logit = (lsym + 2.f * sim) * 2.f;        // / 0.5 temperature
    float p = 1.f / (1.f + expf(-logit));
    p = (p > 0.6f) ? p * 1.2f : p * 0.8f;
    p = fminf(fmaxf(p, 0.f), 1.f);

    bool m = (masks[b * NN + i] != 0) && (masks[b * NN + j] != 0) && (g_active[b] != 0);
    int idx = (b * NN + i) * NN + j;
    out[idx] = m ? p : 0.f;
    if (write_logits) out[BB * NN * NN + idx] = m ? logit : 0.f;
}

// ---------------- launch ----------------
extern "C" void kernel_launch(void* const* d_in, const int* in_sizes, int n_in,
                              void* d_out, int out_size) {
    const float* nf    = (const float*)d_in[0];
    const int*   masks = (const int*)  d_in[1];
    const float *W1, *b1, *W2, *b2, *W3, *b3, *W4, *b4;
    const float *g1, *be1, *m1, *v1, *g2, *be2, *m2, *v2, *g3, *be3, *m3, *v3;

    if (n_in >= 22 && in_sizes[4] == 8192) {
        // setup_inputs dict order: W1,b1..W4,b4 then g/be/m/v blocks
        W1 = (const float*)d_in[2];  b1 = (const float*)d_in[3];
        W2 = (const float*)d_in[4];  b2 = (const float*)d_in[5];
        W3 = (const float*)d_in[6];  b3 = (const float*)d_in[7];
        W4 = (const float*)d_in[8];  b4 = (const float*)d_in[9];
        g1 = (const float*)d_in[10]; be1 = (const float*)d_in[11];
        m1 = (const float*)d_in[12]; v1  = (const float*)d_in[13];
        g2 = (const float*)d_in[14]; be2 = (const float*)d_in[15];
        m2 = (const float*)d_in[16]; v2  = (const float*)d_in[17];
        g3 = (const float*)d_in[18]; be3 = (const float*)d_in[19];
        m3 = (const float*)d_in[20]; v3  = (const float*)d_in[21];
    } else {
        // reference() signature order
        W1 = (const float*)d_in[2];  b1 = (const float*)d_in[3];
        g1 = (const float*)d_in[4];  be1 = (const float*)d_in[5];
        m1 = (const float*)d_in[6];  v1  = (const float*)d_in[7];
        W2 = (const float*)d_in[8];  b2 = (const float*)d_in[9];
        g2 = (const float*)d_in[10]; be2 = (const float*)d_in[11];
        m2 = (const float*)d_in[12]; v2  = (const float*)d_in[13];
        W3 = (const float*)d_in[14]; b3 = (const float*)d_in[15];
        g3 = (const float*)d_in[16]; be3 = (const float*)d_in[17];
        m3 = (const float*)d_in[18]; v3  = (const float*)d_in[19];
        W4 = (const float*)d_in[20]; b4 = (const float*)d_in[21];
    }

    k_fold<<<1, 128>>>(W2, b2, g2, be2, m2, v2,
                       W3, b3, g3, be3, m3, v3, W4, b4);
    k_nodes<<<BB * NN, 128>>>(nf, W1, b1, g1, be1, m1, v1);
    k_active<<<1, 256>>>(masks);
    k_main<<<dim3(NN / TJ, NN / TI, BB), 256>>>();
    int wl = (out_size >= 2 * BB * NN * NN) ? 1 : 0;
    k_epi<<<dim3(NN / 32, NN / 32, BB), dim3(32, 32)>>>(masks, (float*)d_out, wl);
}